// round 8
// baseline (speedup 1.0000x reference)
#include <cuda_runtime.h>
#include <cuda_fp16.h>
#include <cstdint>

// ---------------------------------------------------------------------------
// Problem constants
// ---------------------------------------------------------------------------
#define B_   16
#define H_   64
#define W_   64
#define C_   256
#define KE   4
#define F_   256
#define HW_  (H_ * W_)
#define KTOT 2304
#define PER_E (9 * C_ * F_)

// GEMM tiling: CTA 128x128x32, 4 warps, warp tile 64x64
#define BM 128
#define BN 128
#define BK 32
#define NITER 72
#define STAGES 4
#define A_ROW_BYTES 80               // 64B data + 16B pad (conflict-free ldmatrix)
#define A_STAGE (BM * A_ROW_BYTES)   // 10240
#define B_STAGE (BK * BN * 2)        // 8192
#define STG_BYTES (A_STAGE + B_STAGE)
#define SMEM_TOTAL (STAGES * STG_BYTES)   // 73728

// ---------------------------------------------------------------------------
// Device scratch
// ---------------------------------------------------------------------------
__device__ float g_partial[B_ * 16 * C_];
__device__ float g_att[B_ * KE];
__device__ float g_bias[B_ * F_];
__device__ __align__(16) __half g_in_h[B_ * HW_ * C_];
__device__ __align__(16) __half g_w[B_ * KTOT * F_];

// ---------------------------------------------------------------------------
// PTX helpers
// ---------------------------------------------------------------------------
__device__ __forceinline__ uint32_t smem_u32(const void* p) {
    uint32_t a;
    asm("{ .reg .u64 t; cvta.to.shared.u64 t, %1; cvt.u32.u64 %0, t; }" : "=r"(a) : "l"(p));
    return a;
}
#define CP_ASYNC16(dst, src, ok) \
    asm volatile("{\n\t.reg .pred p;\n\t.reg .b32 sz;\n\tsetp.ne.u32 p, %2, 0;\n\tselp.b32 sz, 16, 0, p;\n\tcp.async.cg.shared.global [%0], [%1], 16, sz;\n\t}" \
        :: "r"(dst), "l"(src), "r"((unsigned)(ok)) : "memory")
#define CP_COMMIT() asm volatile("cp.async.commit_group;" ::: "memory")
#define CP_WAIT2()  asm volatile("cp.async.wait_group 2;" ::: "memory")

#define LDSM_X4(r0, r1, r2, r3, a) \
    asm volatile("ldmatrix.sync.aligned.m8n8.x4.shared.b16 {%0,%1,%2,%3}, [%4];" \
        : "=r"(r0), "=r"(r1), "=r"(r2), "=r"(r3) : "r"(a))
#define LDSM_X4_T(r0, r1, r2, r3, a) \
    asm volatile("ldmatrix.sync.aligned.m8n8.x4.trans.shared.b16 {%0,%1,%2,%3}, [%4];" \
        : "=r"(r0), "=r"(r1), "=r"(r2), "=r"(r3) : "r"(a))

#define MMA16816(c0, c1, c2, c3, a0, a1, a2, a3, b0, b1) \
    asm volatile("mma.sync.aligned.m16n8k16.row.col.f32.f16.f16.f32 " \
        "{%0,%1,%2,%3}, {%4,%5,%6,%7}, {%8,%9}, {%0,%1,%2,%3};" \
        : "+f"(c0), "+f"(c1), "+f"(c2), "+f"(c3) \
        : "r"(a0), "r"(a1), "r"(a2), "r"(a3), "r"(b0), "r"(b1))

// ---------------------------------------------------------------------------
// 1) Fused pooling partials + fp16 convert (reads inputs once)
// ---------------------------------------------------------------------------
__global__ void pool_half_kernel(const float* __restrict__ in) {
    int b = blockIdx.y, s = blockIdx.x, c = threadIdx.x;
    long base = ((long)b * HW_ + s * 256) * C_ + c;
    const float* p = in + base;
    __half* q = g_in_h + base;
    float sum = 0.f;
#pragma unroll 4
    for (int i = 0; i < 256; i++) {
        float v = p[i * C_];
        sum += v;
        q[i * C_] = __float2half_rn(v);
    }
    g_partial[(b * 16 + s) * C_ + c] = sum;
}

// ---------------------------------------------------------------------------
// 2) Routing
// ---------------------------------------------------------------------------
__global__ void route_kernel(const float* __restrict__ w1, const float* __restrict__ b1,
                             const float* __restrict__ w2, const float* __restrict__ b2,
                             const float* __restrict__ biases) {
    __shared__ float pool[C_];
    __shared__ float a1[64];
    __shared__ float att[KE];
    int b = blockIdx.x, t = threadIdx.x;

    float sum = 0.f;
#pragma unroll
    for (int s = 0; s < 16; s++) sum += g_partial[(b * 16 + s) * C_ + t];
    pool[t] = sum * (1.0f / (float)HW_);
    __syncthreads();

    if (t < 64) {
        float v = b1[t];
#pragma unroll 4
        for (int c = 0; c < C_; c++) v += pool[c] * w1[c * 64 + t];
        a1[t] = fmaxf(v, 0.f);
    }
    __syncthreads();
    if (t < KE) {
        float v = b2[t];
#pragma unroll
        for (int j = 0; j < 64; j++) v += a1[j] * w2[j * KE + t];
        att[t] = v;
    }
    __syncthreads();
    if (t == 0) {
        float m = att[0];
        for (int e = 1; e < KE; e++) m = fmaxf(m, att[e]);
        float ex[KE], s2 = 0.f;
        for (int e = 0; e < KE; e++) { ex[e] = expf(att[e] - m); s2 += ex[e]; }
        float inv = 1.0f / s2;
        for (int e = 0; e < KE; e++) { att[e] = ex[e] * inv; g_att[b * KE + e] = att[e]; }
    }
    __syncthreads();
    float bv = 0.f;
#pragma unroll
    for (int e = 0; e < KE; e++) bv += att[e] * biases[e * F_ + t];
    g_bias[b * F_ + t] = bv;
}

// ---------------------------------------------------------------------------
// 3) Combine experts -> fp16 [b][k][f]. One pass over expert kernels, all b.
// ---------------------------------------------------------------------------
__global__ void combine_h_kernel(const float* __restrict__ kernels) {
    __shared__ float satt[B_ * KE];
    int t = threadIdx.x;
    if (t < B_ * KE) satt[t] = g_att[t];
    __syncthreads();

    long off = ((long)blockIdx.x * blockDim.x + t) * 4;
    float4 k0 = *(const float4*)(kernels + 0L * PER_E + off);
    float4 k1 = *(const float4*)(kernels + 1L * PER_E + off);
    float4 k2 = *(const float4*)(kernels + 2L * PER_E + off);
    float4 k3 = *(const float4*)(kernels + 3L * PER_E + off);

#pragma unroll
    for (int b = 0; b < B_; b++) {
        float a0 = satt[b * KE + 0], a1v = satt[b * KE + 1];
        float a2 = satt[b * KE + 2], a3 = satt[b * KE + 3];
        float rx = a0 * k0.x + a1v * k1.x + a2 * k2.x + a3 * k3.x;
        float ry = a0 * k0.y + a1v * k1.y + a2 * k2.y + a3 * k3.y;
        float rz = a0 * k0.z + a1v * k1.z + a2 * k2.z + a3 * k3.z;
        float rw = a0 * k0.w + a1v * k1.w + a2 * k2.w + a3 * k3.w;
        __half2 h[2];
        h[0] = __floats2half2_rn(rx, ry);
        h[1] = __floats2half2_rn(rz, rw);
        *(uint2*)(g_w + (long)b * PER_E + off) = *(uint2*)h;
    }
}

// ---------------------------------------------------------------------------
// 4) Implicit-GEMM conv: 4 warps, 64x64 warp tiles (halves LDSM duplication).
// ---------------------------------------------------------------------------
__global__ __launch_bounds__(128, 2)
void conv_mma_kernel(float* __restrict__ out) {
    extern __shared__ __align__(1024) char smem[];
    uint32_t sb = smem_u32(smem);
    int tid = threadIdx.x;
    int lane = tid & 31, wid = tid >> 5;
    int wm = wid >> 1, wn = wid & 1;          // 2 x 2 warp grid, warp tile 64x64
    int b = blockIdx.z;
    int m0 = blockIdx.x * BM;
    int n0 = blockIdx.y * BN;

    float acc[4][8][4];
#pragma unroll
    for (int i = 0; i < 4; i++)
#pragma unroll
        for (int j = 0; j < 8; j++)
#pragma unroll
            for (int k = 0; k < 4; k++) acc[i][j][k] = 0.f;

    const long inb = (long)b * HW_ * C_;
    const long wbb = (long)b * (long)KTOT * F_;

    // A loads: one row per thread (tid = row 0..127), 4x16B chunks
    // B loads: kk = tid & 31, ch0 = tid >> 5, 4 chunks ch0+4i
    const int b_kk = tid & 31;
    const int b_ch0 = tid >> 5;

    auto load_stage = [&](int stage, int kt) {
        uint32_t st = sb + stage * STG_BYTES;
        int r = kt >> 3;
        int cbase = (kt & 7) << 5;
        int ky = r / 3 - 1, kx = r % 3 - 1;
        {
            int m = m0 + tid;
            int h = m >> 6, w = m & 63;
            int ih = h + ky, iw = w + kx;
            unsigned ok = ((unsigned)ih < H_) & ((unsigned)iw < W_);
            const __half* src = g_in_h + (ok ? (inb + ((long)((ih << 6) + iw)) * C_ + cbase) : 0);
            uint32_t d = st + tid * A_ROW_BYTES;
#pragma unroll
            for (int i = 0; i < 4; i++)
                CP_ASYNC16(d + i * 16, src + i * 8, ok);
        }
        {
            const __half* srcb = g_w + wbb + ((long)(r * C_ + cbase + b_kk)) * F_ + n0;
            uint32_t db = st + A_STAGE + b_kk * 256;
#pragma unroll
            for (int i = 0; i < 4; i++) {
                int ch = b_ch0 + i * 4;
                CP_ASYNC16(db + ((ch ^ (b_kk & 7)) << 4), srcb + ch * 8, 1u);
            }
        }
    };

#pragma unroll
    for (int s = 0; s < 3; s++) { load_stage(s, s); CP_COMMIT(); }

    // per-warp invariant ldsm addressing
    const int a_lrow = wm * 64 + ((lane >> 3) & 1) * 8 + (lane & 7);
    const int a_ksel = (lane >> 4);
    const int b_klane = ((lane >> 3) & 1) * 8 + (lane & 7);

    uint32_t af[2][4][4];   // [ksbuf][mt][frag]
    uint32_t bf[2][4][4];   // [ksbuf][p][frag], p = n16-chunk 0..3 (64 cols)

#define LOAD_FRAGS(buf, ks, stA, stB) do { \
    _Pragma("unroll") \
    for (int mt = 0; mt < 4; mt++) \
        LDSM_X4(af[buf][mt][0], af[buf][mt][1], af[buf][mt][2], af[buf][mt][3], \
                (stA) + (a_lrow + mt * 16) * A_ROW_BYTES + ((ks) * 2 + a_ksel) * 16); \
    _Pragma("unroll") \
    for (int p = 0; p < 4; p++) { \
        int kkl = (ks) * 16 + b_klane; \
        int nch = wn * 8 + p * 2 + (lane >> 4); \
        LDSM_X4_T(bf[buf][p][0], bf[buf][p][1], bf[buf][p][2], bf[buf][p][3], \
                  (stB) + kkl * 256 + ((nch ^ (kkl & 7)) << 4)); \
    } \
} while (0)

#define DO_MMAS(buf) do { \
    _Pragma("unroll") \
    for (int mt = 0; mt < 4; mt++) { \
        _Pragma("unroll") \
        for (int ng = 0; ng < 8; ng++) { \
            uint32_t bb0 = bf[buf][ng >> 1][(ng & 1) * 2]; \
            uint32_t bb1 = bf[buf][ng >> 1][(ng & 1) * 2 + 1]; \
            MMA16816(acc[mt][ng][0], acc[mt][ng][1], acc[mt][ng][2], acc[mt][ng][3], \
                     af[buf][mt][0], af[buf][mt][1], af[buf][mt][2], af[buf][mt][3], bb0, bb1); \
        } \
    } \
} while (0)

    for (int kt = 0; kt < NITER; kt++) {
        CP_WAIT2();
        __syncthreads();

        uint32_t stA = sb + ((kt & 3) * STG_BYTES);
        uint32_t stB = stA + A_STAGE;

        LOAD_FRAGS(0, 0, stA, stB);

        if (kt + 3 < NITER) load_stage((kt + 3) & 3, kt + 3);
        CP_COMMIT();

        LOAD_FRAGS(1, 1, stA, stB);
        DO_MMAS(0);
        DO_MMAS(1);
    }

    // epilogue: bias + store
#pragma unroll
    for (int mt = 0; mt < 4; mt++) {
        int row0 = m0 + wm * 64 + mt * 16 + (lane >> 2);
        float* p0 = out + ((long)b * HW_ + row0) * F_;
        float* p1 = p0 + 8L * F_;
#pragma unroll
        for (int ng = 0; ng < 8; ng++) {
            int col = n0 + wn * 64 + ng * 8 + (lane & 3) * 2;
            float2 bias = *(const float2*)(g_bias + b * F_ + col);
            float2 v0 = make_float2(acc[mt][ng][0] + bias.x, acc[mt][ng][1] + bias.y);
            float2 v1 = make_float2(acc[mt][ng][2] + bias.x, acc[mt][ng][3] + bias.y);
            *(float2*)(p0 + col) = v0;
            *(float2*)(p1 + col) = v1;
        }
    }
}

// ---------------------------------------------------------------------------
// Launch
// ---------------------------------------------------------------------------
extern "C" void kernel_launch(void* const* d_in, const int* in_sizes, int n_in,
                              void* d_out, int out_size) {
    const float* inputs  = (const float*)d_in[0];
    const float* kernels = (const float*)d_in[1];
    const float* biases  = (const float*)d_in[2];
    const float* w1      = (const float*)d_in[3];
    const float* b1      = (const float*)d_in[4];
    const float* w2      = (const float*)d_in[5];
    const float* b2      = (const float*)d_in[6];
    float* out = (float*)d_out;

    static int smem_set = 0;
    if (!smem_set) {
        cudaFuncSetAttribute(conv_mma_kernel, cudaFuncAttributeMaxDynamicSharedMemorySize, SMEM_TOTAL);
        smem_set = 1;
    }

    pool_half_kernel<<<dim3(16, B_), 256>>>(inputs);
    route_kernel<<<B_, 256>>>(w1, b1, w2, b2, biases);
    combine_h_kernel<<<PER_E / 4 / 256, 256>>>(kernels);
    conv_mma_kernel<<<dim3(HW_ / BM, F_ / BN, B_), 128, SMEM_TOTAL>>>(out);
}

// round 10
// speedup vs baseline: 1.7302x; 1.7302x over previous
#include <cuda_runtime.h>
#include <cuda_fp16.h>
#include <cstdint>

// ---------------------------------------------------------------------------
// Problem constants
// ---------------------------------------------------------------------------
#define B_   16
#define H_   64
#define W_   64
#define C_   256
#define KE   4
#define F_   256
#define HW_  (H_ * W_)
#define KTOT 2304
#define PER_E (9 * C_ * F_)

// Conv tiling: CTA = 128 m (2 image rows) x 128 n, K chunked as 4 x (64ch) x 9 taps
#define BM 128
#define BN 128
#define NCHUNK 4                 // C_ / 64
#define NTAP 9
#define NJ (NCHUNK * NTAP)       // 36

// A halo tile: 4 image rows x 66 padded pixels, 64 ch fp16 = 128B data + 16B pad
#define A_SLOTS 264              // 4 * 66
#define A_PITCH 144
#define SB_A 0
#define SB_B 38912               // 264*144 = 38016, aligned up
#define B_STG 16384              // 64 k-rows x 128 cols fp16
#define SMEM_TOTAL (SB_B + 3 * B_STG)   // 88064

// ---------------------------------------------------------------------------
// Device scratch
// ---------------------------------------------------------------------------
__device__ float g_partial[B_ * 16 * C_];
__device__ float g_att[B_ * KE];
__device__ float g_bias[B_ * F_];
__device__ __align__(16) __half g_in_h[B_ * HW_ * C_];
__device__ __align__(16) __half g_w[B_ * KTOT * F_];

// ---------------------------------------------------------------------------
// PTX helpers
// ---------------------------------------------------------------------------
__device__ __forceinline__ uint32_t smem_u32(const void* p) {
    uint32_t a;
    asm("{ .reg .u64 t; cvta.to.shared.u64 t, %1; cvt.u32.u64 %0, t; }" : "=r"(a) : "l"(p));
    return a;
}
#define CP_ASYNC16(dst, src, ok) \
    asm volatile("{\n\t.reg .pred p;\n\t.reg .b32 sz;\n\tsetp.ne.u32 p, %2, 0;\n\tselp.b32 sz, 16, 0, p;\n\tcp.async.cg.shared.global [%0], [%1], 16, sz;\n\t}" \
        :: "r"(dst), "l"(src), "r"((unsigned)(ok)) : "memory")
#define CP_COMMIT() asm volatile("cp.async.commit_group;" ::: "memory")

#define LDSM_X4(r0, r1, r2, r3, a) \
    asm volatile("ldmatrix.sync.aligned.m8n8.x4.shared.b16 {%0,%1,%2,%3}, [%4];" \
        : "=r"(r0), "=r"(r1), "=r"(r2), "=r"(r3) : "r"(a))
#define LDSM_X4_T(r0, r1, r2, r3, a) \
    asm volatile("ldmatrix.sync.aligned.m8n8.x4.trans.shared.b16 {%0,%1,%2,%3}, [%4];" \
        : "=r"(r0), "=r"(r1), "=r"(r2), "=r"(r3) : "r"(a))

#define MMA16816(c0, c1, c2, c3, a0, a1, a2, a3, b0, b1) \
    asm volatile("mma.sync.aligned.m16n8k16.row.col.f32.f16.f16.f32 " \
        "{%0,%1,%2,%3}, {%4,%5,%6,%7}, {%8,%9}, {%0,%1,%2,%3};" \
        : "+f"(c0), "+f"(c1), "+f"(c2), "+f"(c3) \
        : "r"(a0), "r"(a1), "r"(a2), "r"(a3), "r"(b0), "r"(b1))

// ---------------------------------------------------------------------------
// 1) Fused pooling partials + fp16 convert (reads inputs once)
// ---------------------------------------------------------------------------
__global__ void pool_half_kernel(const float* __restrict__ in) {
    int b = blockIdx.y, s = blockIdx.x, c = threadIdx.x;
    long base = ((long)b * HW_ + s * 256) * C_ + c;
    const float* p = in + base;
    __half* q = g_in_h + base;
    float sum = 0.f;
#pragma unroll 4
    for (int i = 0; i < 256; i++) {
        float v = p[i * C_];
        sum += v;
        q[i * C_] = __float2half_rn(v);
    }
    g_partial[(b * 16 + s) * C_ + c] = sum;
}

// ---------------------------------------------------------------------------
// 2) Routing
// ---------------------------------------------------------------------------
__global__ void route_kernel(const float* __restrict__ w1, const float* __restrict__ b1,
                             const float* __restrict__ w2, const float* __restrict__ b2,
                             const float* __restrict__ biases) {
    __shared__ float pool[C_];
    __shared__ float a1[64];
    __shared__ float att[KE];
    int b = blockIdx.x, t = threadIdx.x;

    float sum = 0.f;
#pragma unroll
    for (int s = 0; s < 16; s++) sum += g_partial[(b * 16 + s) * C_ + t];
    pool[t] = sum * (1.0f / (float)HW_);
    __syncthreads();

    if (t < 64) {
        float v = b1[t];
#pragma unroll 4
        for (int c = 0; c < C_; c++) v += pool[c] * w1[c * 64 + t];
        a1[t] = fmaxf(v, 0.f);
    }
    __syncthreads();
    if (t < KE) {
        float v = b2[t];
#pragma unroll
        for (int j = 0; j < 64; j++) v += a1[j] * w2[j * KE + t];
        att[t] = v;
    }
    __syncthreads();
    if (t == 0) {
        float m = att[0];
        for (int e = 1; e < KE; e++) m = fmaxf(m, att[e]);
        float ex[KE], s2 = 0.f;
        for (int e = 0; e < KE; e++) { ex[e] = expf(att[e] - m); s2 += ex[e]; }
        float inv = 1.0f / s2;
        for (int e = 0; e < KE; e++) { att[e] = ex[e] * inv; g_att[b * KE + e] = att[e]; }
    }
    __syncthreads();
    float bv = 0.f;
#pragma unroll
    for (int e = 0; e < KE; e++) bv += att[e] * biases[e * F_ + t];
    g_bias[b * F_ + t] = bv;
}

// ---------------------------------------------------------------------------
// 3) Combine experts -> fp16 [b][k][f]. One pass over expert kernels, all b.
// ---------------------------------------------------------------------------
__global__ void combine_h_kernel(const float* __restrict__ kernels) {
    __shared__ float satt[B_ * KE];
    int t = threadIdx.x;
    if (t < B_ * KE) satt[t] = g_att[t];
    __syncthreads();

    long off = ((long)blockIdx.x * blockDim.x + t) * 4;
    float4 k0 = *(const float4*)(kernels + 0L * PER_E + off);
    float4 k1 = *(const float4*)(kernels + 1L * PER_E + off);
    float4 k2 = *(const float4*)(kernels + 2L * PER_E + off);
    float4 k3 = *(const float4*)(kernels + 3L * PER_E + off);

#pragma unroll
    for (int b = 0; b < B_; b++) {
        float a0 = satt[b * KE + 0], a1v = satt[b * KE + 1];
        float a2 = satt[b * KE + 2], a3 = satt[b * KE + 3];
        float rx = a0 * k0.x + a1v * k1.x + a2 * k2.x + a3 * k3.x;
        float ry = a0 * k0.y + a1v * k1.y + a2 * k2.y + a3 * k3.y;
        float rz = a0 * k0.z + a1v * k1.z + a2 * k2.z + a3 * k3.z;
        float rw = a0 * k0.w + a1v * k1.w + a2 * k2.w + a3 * k3.w;
        __half2 h[2];
        h[0] = __floats2half2_rn(rx, ry);
        h[1] = __floats2half2_rn(rz, rw);
        *(uint2*)(g_w + (long)b * PER_E + off) = *(uint2*)h;
    }
}

// ---------------------------------------------------------------------------
// 4) Conv: halo-resident A (loaded once per 64-ch chunk, reused by all 9 taps
//    via shifted ldmatrix addressing), 3-stage cp.async B ring per tap.
//    256 threads, 2x4 warp grid, warp tile 64x32.
// ---------------------------------------------------------------------------
__global__ __launch_bounds__(256, 2)
void conv_mma_kernel(float* __restrict__ out) {
    extern __shared__ __align__(1024) char smem[];
    uint32_t sb = smem_u32(smem);
    int tid = threadIdx.x;
    int lane = tid & 31, wid = tid >> 5;
    int wm = wid >> 2, wn = wid & 3;     // 2 x 4 warp grid
    int b = blockIdx.z;
    int bx = blockIdx.x;                 // image-row pair index (m0 = bx*128)
    int n0 = blockIdx.y * BN;

    float acc[4][4][4];
#pragma unroll
    for (int i = 0; i < 4; i++)
#pragma unroll
        for (int j = 0; j < 4; j++)
#pragma unroll
            for (int k = 0; k < 4; k++) acc[i][j][k] = 0.f;

    const long inb = (long)b * HW_ * C_;
    const long wbb = (long)b * (long)KTOT * F_;

    // --- A halo loader: 264 slots (4 rows x 66 pixels) x 8 chunks of 16B ---
    auto loadA = [&](int cchunk) {
#pragma unroll
        for (int i = 0; i < 9; i++) {
            int idx = tid + i * 256;
            if (idx < A_SLOTS * 8) {
                int s = idx >> 3, ch = idx & 7;
                int hl = s / 66, ww = s % 66;
                int ih = 2 * bx - 1 + hl, w = ww - 1;
                unsigned ok = ((unsigned)ih < H_) & ((unsigned)w < W_);
                const __half* src = g_in_h +
                    (ok ? (inb + ((long)(ih * 64 + w)) * C_ + cchunk * 64 + ch * 8) : 0);
                CP_ASYNC16(sb + SB_A + s * A_PITCH + ch * 16, src, ok);
            }
        }
    };

    // --- B loader for global iter j = chunk*9 + tap: 64 k-rows x 128 cols ---
    auto loadB = [&](int j) {
        int cchunk = j / 9, tap = j % 9;
        uint32_t st = sb + SB_B + (j % 3) * B_STG;
        long kbase = wbb + ((long)(tap * C_ + cchunk * 64)) * F_ + n0;
#pragma unroll
        for (int i = 0; i < 4; i++) {
            int idx = tid + i * 256;
            int kk = idx >> 4, ch = idx & 15;
            CP_ASYNC16(st + kk * 256 + ((ch ^ (kk & 7)) << 4),
                       g_w + kbase + (long)kk * F_ + ch * 8, 1u);
        }
    };

    // prefetch B(0), B(1)
    loadB(0); CP_COMMIT();
    loadB(1); CP_COMMIT();

    // per-lane invariants
    const int laneA = (lane & 7) + ((lane >> 3) & 1) * 8;  // 0..15 row-within-tile
    const int kchunk = lane >> 4;                           // 16B column select
    const int b_klane = ((lane >> 3) & 1) * 8 + (lane & 7);

    for (int c = 0; c < NCHUNK; c++) {
        __syncthreads();                  // all warps done reading A(c-1)
        loadA(c);
        CP_COMMIT();

#pragma unroll 1
        for (int t = 0; t < NTAP; t++) {
            int j = c * 9 + t;
            // wait for B(j) (+ A(c) at t==0); groups newer than B(j): B(j+1) only
            if (t == 0) {
                asm volatile("cp.async.wait_group 0;" ::: "memory");
            } else if (j + 1 <= NJ - 1) {
                asm volatile("cp.async.wait_group 1;" ::: "memory");
            } else {
                asm volatile("cp.async.wait_group 0;" ::: "memory");
            }
            __syncthreads();              // publish B(j); also WAR for B(j+2)'s stage

            if (j + 2 <= NJ - 1) { loadB(j + 2); CP_COMMIT(); }

            int ky = t / 3 - 1, kx = t % 3 - 1;
            // A base for this warp+tap: image row (wm+ky), pixel shift kx
            uint32_t abase = sb + SB_A +
                (uint32_t)(((wm + ky + 1) * 66 + kx + 1 + laneA) * A_PITCH) + kchunk * 16;
            uint32_t bst = sb + SB_B + (j % 3) * B_STG;

#pragma unroll
            for (int ks = 0; ks < 4; ks++) {
                uint32_t af[4][4];
#pragma unroll
                for (int mt = 0; mt < 4; mt++)
                    LDSM_X4(af[mt][0], af[mt][1], af[mt][2], af[mt][3],
                            abase + mt * (16 * A_PITCH) + ks * 32);
                uint32_t bfr[2][4];
#pragma unroll
                for (int p = 0; p < 2; p++) {
                    int kk = ks * 16 + b_klane;
                    int nch = wn * 4 + p * 2 + (lane >> 4);
                    LDSM_X4_T(bfr[p][0], bfr[p][1], bfr[p][2], bfr[p][3],
                              bst + kk * 256 + ((nch ^ (kk & 7)) << 4));
                }
#pragma unroll
                for (int mt = 0; mt < 4; mt++) {
#pragma unroll
                    for (int ng = 0; ng < 4; ng++) {
                        uint32_t b0 = bfr[ng >> 1][(ng & 1) * 2];
                        uint32_t b1 = bfr[ng >> 1][(ng & 1) * 2 + 1];
                        MMA16816(acc[mt][ng][0], acc[mt][ng][1], acc[mt][ng][2], acc[mt][ng][3],
                                 af[mt][0], af[mt][1], af[mt][2], af[mt][3], b0, b1);
                    }
                }
            }
        }
    }

    // epilogue: bias + store
    float2 bias[4];
#pragma unroll
    for (int ng = 0; ng < 4; ng++) {
        int col = n0 + wn * 32 + ng * 8 + (lane & 3) * 2;
        bias[ng] = *(const float2*)(g_bias + b * F_ + col);
    }
#pragma unroll
    for (int mt = 0; mt < 4; mt++) {
        int row0 = bx * BM + wm * 64 + mt * 16 + (lane >> 2);
        float* p0 = out + ((long)b * HW_ + row0) * F_;
        float* p1 = p0 + 8L * F_;
#pragma unroll
        for (int ng = 0; ng < 4; ng++) {
            int col = n0 + wn * 32 + ng * 8 + (lane & 3) * 2;
            float2 v0 = make_float2(acc[mt][ng][0] + bias[ng].x, acc[mt][ng][1] + bias[ng].y);
            float2 v1 = make_float2(acc[mt][ng][2] + bias[ng].x, acc[mt][ng][3] + bias[ng].y);
            *(float2*)(p0 + col) = v0;
            *(float2*)(p1 + col) = v1;
        }
    }
}

// ---------------------------------------------------------------------------
// Launch
// ---------------------------------------------------------------------------
extern "C" void kernel_launch(void* const* d_in, const int* in_sizes, int n_in,
                              void* d_out, int out_size) {
    const float* inputs  = (const float*)d_in[0];
    const float* kernels = (const float*)d_in[1];
    const float* biases  = (const float*)d_in[2];
    const float* w1      = (const float*)d_in[3];
    const float* b1      = (const float*)d_in[4];
    const float* w2      = (const float*)d_in[5];
    const float* b2      = (const float*)d_in[6];
    float* out = (float*)d_out;

    static int smem_set = 0;
    if (!smem_set) {
        cudaFuncSetAttribute(conv_mma_kernel, cudaFuncAttributeMaxDynamicSharedMemorySize, SMEM_TOTAL);
        smem_set = 1;
    }

    pool_half_kernel<<<dim3(16, B_), 256>>>(inputs);
    route_kernel<<<B_, 256>>>(w1, b1, w2, b2, biases);
    combine_h_kernel<<<PER_E / 4 / 256, 256>>>(kernels);
    conv_mma_kernel<<<dim3(HW_ / BM, F_ / BN, B_), 256, SMEM_TOTAL>>>(out);
}

// round 12
// speedup vs baseline: 1.9344x; 1.1180x over previous
#include <cuda_runtime.h>
#include <cuda_fp16.h>
#include <cstdint>

// ---------------------------------------------------------------------------
// Problem constants
// ---------------------------------------------------------------------------
#define B_   16
#define H_   64
#define W_   64
#define C_   256
#define KE   4
#define F_   256
#define HW_  (H_ * W_)
#define KTOT 2304
#define PER_E (9 * C_ * F_)

// Conv tiling: CTA = 128 m (2 image rows) x 128 n, K chunked as 4 x (64ch) x 9 taps
#define BM 128
#define BN 128
#define NCHUNK 4                 // C_ / 64
#define NTAP 9
#define NJ (NCHUNK * NTAP)       // 36

// A halo tile: 4 image rows x 66 padded pixels, 64 ch fp16 = 128B data + 16B pad
#define A_SLOTS 264              // 4 * 66
#define A_PITCH 144
#define SB_A 0
#define SB_B 38912               // 264*144 = 38016, aligned up
#define B_STG 16384              // 64 k-rows x 128 cols fp16
#define BSTAGES 4
#define SMEM_TOTAL (SB_B + BSTAGES * B_STG)   // 104448

// ---------------------------------------------------------------------------
// Device scratch
// ---------------------------------------------------------------------------
__device__ float g_partial[B_ * 64 * C_];
__device__ float g_att[B_ * KE];
__device__ float g_bias[B_ * F_];
__device__ __align__(16) __half g_in_h[B_ * HW_ * C_];
__device__ __align__(16) __half g_w[B_ * KTOT * F_];

// ---------------------------------------------------------------------------
// PTX helpers
// ---------------------------------------------------------------------------
__device__ __forceinline__ uint32_t smem_u32(const void* p) {
    uint32_t a;
    asm("{ .reg .u64 t; cvta.to.shared.u64 t, %1; cvt.u32.u64 %0, t; }" : "=r"(a) : "l"(p));
    return a;
}
#define CP_ASYNC16(dst, src, ok) \
    asm volatile("{\n\t.reg .pred p;\n\t.reg .b32 sz;\n\tsetp.ne.u32 p, %2, 0;\n\tselp.b32 sz, 16, 0, p;\n\tcp.async.cg.shared.global [%0], [%1], 16, sz;\n\t}" \
        :: "r"(dst), "l"(src), "r"((unsigned)(ok)) : "memory")
#define CP_COMMIT() asm volatile("cp.async.commit_group;" ::: "memory")

#define LDSM_X4(r0, r1, r2, r3, a) \
    asm volatile("ldmatrix.sync.aligned.m8n8.x4.shared.b16 {%0,%1,%2,%3}, [%4];" \
        : "=r"(r0), "=r"(r1), "=r"(r2), "=r"(r3) : "r"(a))
#define LDSM_X4_T(r0, r1, r2, r3, a) \
    asm volatile("ldmatrix.sync.aligned.m8n8.x4.trans.shared.b16 {%0,%1,%2,%3}, [%4];" \
        : "=r"(r0), "=r"(r1), "=r"(r2), "=r"(r3) : "r"(a))

#define MMA16816(c0, c1, c2, c3, a0, a1, a2, a3, b0, b1) \
    asm volatile("mma.sync.aligned.m16n8k16.row.col.f32.f16.f16.f32 " \
        "{%0,%1,%2,%3}, {%4,%5,%6,%7}, {%8,%9}, {%0,%1,%2,%3};" \
        : "+f"(c0), "+f"(c1), "+f"(c2), "+f"(c3) \
        : "r"(a0), "r"(a1), "r"(a2), "r"(a3), "r"(b0), "r"(b1))

// ---------------------------------------------------------------------------
// 1) Fused pooling partials + fp16 convert (reads inputs once).
//    grid (64, B_): 64 rows per CTA -> 1024 CTAs for parallelism.
// ---------------------------------------------------------------------------
__global__ void pool_half_kernel(const float* __restrict__ in) {
    int b = blockIdx.y, s = blockIdx.x, c = threadIdx.x;
    long base = ((long)b * HW_ + s * 64) * C_ + c;
    const float* p = in + base;
    __half* q = g_in_h + base;
    float sum = 0.f;
#pragma unroll 8
    for (int i = 0; i < 64; i++) {
        float v = p[i * C_];
        sum += v;
        q[i * C_] = __float2half_rn(v);
    }
    g_partial[(b * 64 + s) * C_ + c] = sum;
}

// ---------------------------------------------------------------------------
// 2) Routing
// ---------------------------------------------------------------------------
__global__ void route_kernel(const float* __restrict__ w1, const float* __restrict__ b1,
                             const float* __restrict__ w2, const float* __restrict__ b2,
                             const float* __restrict__ biases) {
    __shared__ float pool[C_];
    __shared__ float a1[64];
    __shared__ float att[KE];
    int b = blockIdx.x, t = threadIdx.x;

    float sum = 0.f;
#pragma unroll 8
    for (int s = 0; s < 64; s++) sum += g_partial[(b * 64 + s) * C_ + t];
    pool[t] = sum * (1.0f / (float)HW_);
    __syncthreads();

    if (t < 64) {
        float v = b1[t];
#pragma unroll 4
        for (int c = 0; c < C_; c++) v += pool[c] * w1[c * 64 + t];
        a1[t] = fmaxf(v, 0.f);
    }
    __syncthreads();
    if (t < KE) {
        float v = b2[t];
#pragma unroll
        for (int j = 0; j < 64; j++) v += a1[j] * w2[j * KE + t];
        att[t] = v;
    }
    __syncthreads();
    if (t == 0) {
        float m = att[0];
        for (int e = 1; e < KE; e++) m = fmaxf(m, att[e]);
        float ex[KE], s2 = 0.f;
        for (int e = 0; e < KE; e++) { ex[e] = expf(att[e] - m); s2 += ex[e]; }
        float inv = 1.0f / s2;
        for (int e = 0; e < KE; e++) { att[e] = ex[e] * inv; g_att[b * KE + e] = att[e]; }
    }
    __syncthreads();
    float bv = 0.f;
#pragma unroll
    for (int e = 0; e < KE; e++) bv += att[e] * biases[e * F_ + t];
    g_bias[b * F_ + t] = bv;
}

// ---------------------------------------------------------------------------
// 3) Combine experts -> fp16 [b][k][f]. One pass over expert kernels, all b.
// ---------------------------------------------------------------------------
__global__ void combine_h_kernel(const float* __restrict__ kernels) {
    __shared__ float satt[B_ * KE];
    int t = threadIdx.x;
    if (t < B_ * KE) satt[t] = g_att[t];
    __syncthreads();

    long off = ((long)blockIdx.x * blockDim.x + t) * 4;
    float4 k0 = *(const float4*)(kernels + 0L * PER_E + off);
    float4 k1 = *(const float4*)(kernels + 1L * PER_E + off);
    float4 k2 = *(const float4*)(kernels + 2L * PER_E + off);
    float4 k3 = *(const float4*)(kernels + 3L * PER_E + off);

#pragma unroll
    for (int b = 0; b < B_; b++) {
        float a0 = satt[b * KE + 0], a1v = satt[b * KE + 1];
        float a2 = satt[b * KE + 2], a3 = satt[b * KE + 3];
        float rx = a0 * k0.x + a1v * k1.x + a2 * k2.x + a3 * k3.x;
        float ry = a0 * k0.y + a1v * k1.y + a2 * k2.y + a3 * k3.y;
        float rz = a0 * k0.z + a1v * k1.z + a2 * k2.z + a3 * k3.z;
        float rw = a0 * k0.w + a1v * k1.w + a2 * k2.w + a3 * k3.w;
        __half2 h[2];
        h[0] = __floats2half2_rn(rx, ry);
        h[1] = __floats2half2_rn(rz, rw);
        *(uint2*)(g_w + (long)b * PER_E + off) = *(uint2*)h;
    }
}

// ---------------------------------------------------------------------------
// 4) Conv: halo-resident A + 4-stage cp.async B ring (prefetch distance 3).
//    256 threads, 2x4 warp grid, warp tile 64x32.
// ---------------------------------------------------------------------------
__global__ __launch_bounds__(256, 2)
void conv_mma_kernel(float* __restrict__ out) {
    extern __shared__ __align__(1024) char smem[];
    uint32_t sb = smem_u32(smem);
    int tid = threadIdx.x;
    int lane = tid & 31, wid = tid >> 5;
    int wm = wid >> 2, wn = wid & 3;     // 2 x 4 warp grid
    int b = blockIdx.z;
    int bx = blockIdx.x;                 // image-row pair index (m0 = bx*128)
    int n0 = blockIdx.y * BN;

    float acc[4][4][4];
#pragma unroll
    for (int i = 0; i < 4; i++)
#pragma unroll
        for (int j = 0; j < 4; j++)
#pragma unroll
            for (int k = 0; k < 4; k++) acc[i][j][k] = 0.f;

    const long inb = (long)b * HW_ * C_;
    const long wbb = (long)b * (long)KTOT * F_;

    // --- A halo loader: 264 slots (4 rows x 66 pixels) x 8 chunks of 16B ---
    auto loadA = [&](int cchunk) {
#pragma unroll
        for (int i = 0; i < 9; i++) {
            int idx = tid + i * 256;
            if (idx < A_SLOTS * 8) {
                int s = idx >> 3, ch = idx & 7;
                int hl = s / 66, ww = s % 66;
                int ih = 2 * bx - 1 + hl, w = ww - 1;
                unsigned ok = ((unsigned)ih < H_) & ((unsigned)w < W_);
                const __half* src = g_in_h +
                    (ok ? (inb + ((long)(ih * 64 + w)) * C_ + cchunk * 64 + ch * 8) : 0);
                CP_ASYNC16(sb + SB_A + s * A_PITCH + ch * 16, src, ok);
            }
        }
    };

    // --- B loader for global iter j = chunk*9 + tap: 64 k-rows x 128 cols ---
    auto loadB = [&](int j) {
        int cchunk = j / 9, tap = j % 9;
        uint32_t st = sb + SB_B + (j % BSTAGES) * B_STG;
        long kbase = wbb + ((long)(tap * C_ + cchunk * 64)) * F_ + n0;
#pragma unroll
        for (int i = 0; i < 4; i++) {
            int idx = tid + i * 256;
            int kk = idx >> 4, ch = idx & 15;
            CP_ASYNC16(st + kk * 256 + ((ch ^ (kk & 7)) << 4),
                       g_w + kbase + (long)kk * F_ + ch * 8, 1u);
        }
    };

    // prefetch B(0), B(1), B(2)
    loadB(0); CP_COMMIT();
    loadB(1); CP_COMMIT();
    loadB(2); CP_COMMIT();

    // per-lane invariants
    const int laneA = (lane & 7) + ((lane >> 3) & 1) * 8;  // 0..15 row-within-tile
    const int kchunk = lane >> 4;                           // 16B column select
    const int b_klane = ((lane >> 3) & 1) * 8 + (lane & 7);

    for (int c = 0; c < NCHUNK; c++) {
        __syncthreads();                  // all warps done reading A(c-1)
        loadA(c);
        CP_COMMIT();

#pragma unroll 1
        for (int t = 0; t < NTAP; t++) {
            int j = c * 9 + t;
            // Wait for B(j) (and A(c) at t==0). Pending newer groups after the
            // previous tap's issue: B(j+1), B(j+2) (when they exist).
            if (t == 0) {
                asm volatile("cp.async.wait_group 0;" ::: "memory");
            } else {
                int rem = (NJ - 1) - j;   // how many newer B groups may be pending
                if (rem >= 2)      asm volatile("cp.async.wait_group 2;" ::: "memory");
                else if (rem == 1) asm volatile("cp.async.wait_group 1;" ::: "memory");
                else               asm volatile("cp.async.wait_group 0;" ::: "memory");
            }
            __syncthreads();              // publish B(j); WAR for stage (j+3)%4

            if (j + 3 <= NJ - 1) { loadB(j + 3); CP_COMMIT(); }

            int ky = t / 3 - 1, kx = t % 3 - 1;
            // A base for this warp+tap: image row (wm+ky), pixel shift kx
            uint32_t abase = sb + SB_A +
                (uint32_t)(((wm + ky + 1) * 66 + kx + 1 + laneA) * A_PITCH) + kchunk * 16;
            uint32_t bst = sb + SB_B + (j % BSTAGES) * B_STG;

#pragma unroll
            for (int ks = 0; ks < 4; ks++) {
                uint32_t af[4][4];
#pragma unroll
                for (int mt = 0; mt < 4; mt++)
                    LDSM_X4(af[mt][0], af[mt][1], af[mt][2], af[mt][3],
                            abase + mt * (16 * A_PITCH) + ks * 32);
                uint32_t bfr[2][4];
#pragma unroll
                for (int p = 0; p < 2; p++) {
                    int kk = ks * 16 + b_klane;
                    int nch = wn * 4 + p * 2 + (lane >> 4);
                    LDSM_X4_T(bfr[p][0], bfr[p][1], bfr[p][2], bfr[p][3],
                              bst + kk * 256 + ((nch ^ (kk & 7)) << 4));
                }
#pragma unroll
                for (int mt = 0; mt < 4; mt++) {
#pragma unroll
                    for (int ng = 0; ng < 4; ng++) {
                        uint32_t b0 = bfr[ng >> 1][(ng & 1) * 2];
                        uint32_t b1 = bfr[ng >> 1][(ng & 1) * 2 + 1];
                        MMA16816(acc[mt][ng][0], acc[mt][ng][1], acc[mt][ng][2], acc[mt][ng][3],
                                 af[mt][0], af[mt][1], af[mt][2], af[mt][3], b0, b1);
                    }
                }
            }
        }
    }

    // epilogue: bias + store
    float2 bias[4];
#pragma unroll
    for (int ng = 0; ng < 4; ng++) {
        int col = n0 + wn * 32 + ng * 8 + (lane & 3) * 2;
        bias[ng] = *(const float2*)(g_bias + b * F_ + col);
    }
#pragma unroll
    for (int mt = 0; mt < 4; mt++) {
        int row0 = bx * BM + wm * 64 + mt * 16 + (lane >> 2);
        float* p0 = out + ((long)b * HW_ + row0) * F_;
        float* p1 = p0 + 8L * F_;
#pragma unroll
        for (int ng = 0; ng < 4; ng++) {
            int col = n0 + wn * 32 + ng * 8 + (lane & 3) * 2;
            float2 v0 = make_float2(acc[mt][ng][0] + bias[ng].x, acc[mt][ng][1] + bias[ng].y);
            float2 v1 = make_float2(acc[mt][ng][2] + bias[ng].x, acc[mt][ng][3] + bias[ng].y);
            *(float2*)(p0 + col) = v0;
            *(float2*)(p1 + col) = v1;
        }
    }
}

// ---------------------------------------------------------------------------
// Launch
// ---------------------------------------------------------------------------
extern "C" void kernel_launch(void* const* d_in, const int* in_sizes, int n_in,
                              void* d_out, int out_size) {
    const float* inputs  = (const float*)d_in[0];
    const float* kernels = (const float*)d_in[1];
    const float* biases  = (const float*)d_in[2];
    const float* w1      = (const float*)d_in[3];
    const float* b1      = (const float*)d_in[4];
    const float* w2      = (const float*)d_in[5];
    const float* b2      = (const float*)d_in[6];
    float* out = (float*)d_out;

    static int smem_set = 0;
    if (!smem_set) {
        cudaFuncSetAttribute(conv_mma_kernel, cudaFuncAttributeMaxDynamicSharedMemorySize, SMEM_TOTAL);
        smem_set = 1;
    }

    pool_half_kernel<<<dim3(64, B_), 256>>>(inputs);
    route_kernel<<<B_, 256>>>(w1, b1, w2, b2, biases);
    combine_h_kernel<<<PER_E / 4 / 256, 256>>>(kernels);
    conv_mma_kernel<<<dim3(HW_ / BM, F_ / BN, B_), 256, SMEM_TOTAL>>>(out);
}